// round 3
// baseline (speedup 1.0000x reference)
#include <cuda_runtime.h>
#include <cuda_bf16.h>
#include <math.h>
#include <stdint.h>

#define MAXN 100000
#define MAXE 1600000

// Scratch (device globals; no cudaMalloc allowed)
__device__ __align__(16) float g_bufA[MAXN * 64];
__device__ __align__(16) float g_bufB[MAXN * 64];
__device__ __align__(16) int   g_deg[MAXN];
__device__ __align__(16) float g_dinv[MAXN];
__device__ __align__(16) float g_Wc[64 * 64];
__device__ __align__(16) float g_bc[64];
__device__ __align__(16) int   g_esrc[MAXE];
__device__ __align__(16) int   g_edst[MAXE];
__device__ __align__(16) float g_enrm[MAXE];
__device__ int g_is32;   // 1 if edge_index stored as int32, 0 if int64

// ---------------- dtype detection (device-side, deterministic) ----------------
// int64 little-endian values < 2^31 have zero high words at odd 32-bit positions.
// int32 node ids at odd positions are nonzero w.p. 1-1e-5.
__global__ void detect_kernel(const unsigned int* __restrict__ w, int nwords) {
    __shared__ int cnt;
    if (threadIdx.x == 0) cnt = 0;
    __syncthreads();
    int nz = 0;
    for (int i = threadIdx.x; i < 1024; i += blockDim.x) {
        int idx = 2 * i + 1;
        if (idx < nwords && w[idx] != 0u) nz++;
    }
    atomicAdd(&cnt, nz);
    __syncthreads();
    if (threadIdx.x == 0) g_is32 = (cnt > 10) ? 1 : 0;
}

// ---------------- elementwise helpers ----------------

__global__ void zero4_kernel(float4* __restrict__ p, int n4) {
    int i = blockIdx.x * blockDim.x + threadIdx.x;
    if (i < n4) p[i] = make_float4(0.f, 0.f, 0.f, 0.f);
}

// Decode edges (either dtype), pack to int32, count degrees at dst.
__global__ void prep_edges_kernel(const void* __restrict__ ei, int E,
                                  int* __restrict__ esrc, int* __restrict__ edst,
                                  int* __restrict__ deg) {
    int e = blockIdx.x * blockDim.x + threadIdx.x;
    if (e >= E) return;
    int s, d;
    if (g_is32) {
        const int* p = (const int*)ei;
        s = p[e];
        d = p[E + e];
    } else {
        const long long* p = (const long long*)ei;
        s = (int)p[e];
        d = (int)p[E + e];
    }
    esrc[e] = s;
    edst[e] = d;
    atomicAdd(&deg[d], 1);
}

__global__ void dinv_kernel(const int* __restrict__ deg, float* __restrict__ dinv, int n) {
    int i = blockIdx.x * blockDim.x + threadIdx.x;
    if (i < n) dinv[i] = rsqrtf((float)deg[i] + 1.0f);
}

__global__ void enrm_kernel(const int* __restrict__ esrc, const int* __restrict__ edst,
                            const float* __restrict__ dinv, float* __restrict__ enrm, int E) {
    int e = blockIdx.x * blockDim.x + threadIdx.x;
    if (e < E) enrm[e] = dinv[esrc[e]] * dinv[edst[e]];
}

// Wc = W3 @ W4  (64x256 @ 256x64), bc = b3 @ W4 + b4
__global__ void build_wc_kernel(const float* __restrict__ W3, const float* __restrict__ b3,
                                const float* __restrict__ W4, const float* __restrict__ b4,
                                float* __restrict__ Wc, float* __restrict__ bc) {
    int o = blockIdx.x * blockDim.x + threadIdx.x;
    if (o < 64 * 64) {
        int i = o >> 6, j = o & 63;
        float s = 0.f;
        #pragma unroll 8
        for (int k = 0; k < 256; k++) s = fmaf(W3[i * 256 + k], W4[k * 64 + j], s);
        Wc[o] = s;
    } else if (o < 64 * 64 + 64) {
        int j = o - 64 * 64;
        float s = b4[j];
        #pragma unroll 8
        for (int k = 0; k < 256; k++) s = fmaf(b3[k], W4[k * 64 + j], s);
        bc[j] = s;
    }
}

// agg[i][c] = relu(agg[i][c] + h[i][c]*dinv[i]^2 + b[c])   (in place on agg)
__global__ void finalize_kernel(const float* __restrict__ h, float* __restrict__ agg,
                                const float* __restrict__ dinv, const float* __restrict__ b, int n) {
    int idx = blockIdx.x * blockDim.x + threadIdx.x;  // over n*16 float4s
    if (idx >= n * 16) return;
    int node = idx >> 4;
    int c4 = idx & 15;
    float di = dinv[node];
    float sl = di * di;
    float4 hv = ((const float4*)h)[idx];
    float4 av = ((const float4*)agg)[idx];
    float4 bv = ((const float4*)b)[c4];
    float4 o;
    o.x = fmaxf(fmaf(hv.x, sl, av.x) + bv.x, 0.f);
    o.y = fmaxf(fmaf(hv.y, sl, av.y) + bv.y, 0.f);
    o.z = fmaxf(fmaf(hv.z, sl, av.z) + bv.z, 0.f);
    o.w = fmaxf(fmaf(hv.w, sl, av.w) + bv.w, 0.f);
    ((float4*)agg)[idx] = o;
}

// ---------------- edge scatter: agg[dst] += h[src] * norm ----------------
// 4 threads per edge; each thread handles 4 float4s (64B) via vector atomics.

__device__ __forceinline__ void red_add_f4(float* p, float4 v) {
#if defined(CUDART_VERSION) && (CUDART_VERSION >= 12030) && (__CUDA_ARCH__ >= 900)
    atomicAdd(reinterpret_cast<float4*>(p), v);
#else
    atomicAdd(p + 0, v.x);
    atomicAdd(p + 1, v.y);
    atomicAdd(p + 2, v.z);
    atomicAdd(p + 3, v.w);
#endif
}

__global__ void scatter_kernel(const float* __restrict__ h,
                               const int* __restrict__ esrc, const int* __restrict__ edst,
                               const float* __restrict__ enrm,
                               float* __restrict__ agg, int E) {
    int idx = blockIdx.x * blockDim.x + threadIdx.x;
    if (idx >= E * 4) return;
    int e = idx >> 2;
    int q = idx & 3;           // quarter of the 64-ch row
    int s = __ldg(&esrc[e]);
    int d = __ldg(&edst[e]);
    float nrm = __ldg(&enrm[e]);
    const float4* hp = (const float4*)(h + (size_t)s * 64) + q * 4;
    float* ap = agg + (size_t)d * 64 + q * 16;
    #pragma unroll
    for (int j = 0; j < 4; j++) {
        float4 v = __ldg(&hp[j]);
        red_add_f4(ap + j * 4, make_float4(v.x * nrm, v.y * nrm, v.z * nrm, v.w * nrm));
    }
}

// ---------------- skinny GEMM: Y[n,64] = X[n,K] @ W[K,64] (+bias, +log_softmax if FINAL) ----
// Block: 128 threads, 128 rows. Thread microtile: 4 rows x 16 cols.

template <int K, bool FINAL>
__global__ void __launch_bounds__(128, 2)
gemm_kernel(const float* __restrict__ X, const float* __restrict__ W,
            const float* __restrict__ bias, float* __restrict__ Y, int n) {
    extern __shared__ float smem[];
    const int PADK = K + 4;
    float* xs = smem;                  // 128 * PADK
    float* ws = smem + 128 * PADK;     // K * 64

    const int t = threadIdx.x;
    const int row0 = blockIdx.x * 128;

    // load W (coalesced float4)
    {
        const float4* Wv = (const float4*)W;
        float4* wsv = (float4*)ws;
        #pragma unroll
        for (int i = t; i < K * 16; i += 128) wsv[i] = Wv[i];
    }
    // load X tile (coalesced float4, zero-pad past n)
    {
        const int QK = K / 4;
        for (int i = t; i < 128 * QK; i += 128) {
            int r = i / QK, q = i % QK;
            int row = row0 + r;
            float4 v = make_float4(0.f, 0.f, 0.f, 0.f);
            if (row < n) v = ((const float4*)X)[(size_t)row * QK + q];
            *((float4*)&xs[r * PADK + q * 4]) = v;
        }
    }
    __syncthreads();

    const int cg = t & 3;
    const int rg = t >> 2;
    const int col0 = cg * 16;

    float acc[4][16];
    #pragma unroll
    for (int r = 0; r < 4; r++)
        #pragma unroll
        for (int c = 0; c < 16; c++) acc[r][c] = 0.f;

    #pragma unroll 2
    for (int k = 0; k < K; k += 4) {
        float4 xv[4];
        #pragma unroll
        for (int r = 0; r < 4; r++)
            xv[r] = *(const float4*)&xs[(rg + 32 * r) * PADK + k];
        #pragma unroll
        for (int kk = 0; kk < 4; kk++) {
            const float4 w0 = *(const float4*)&ws[(k + kk) * 64 + col0 + 0];
            const float4 w1 = *(const float4*)&ws[(k + kk) * 64 + col0 + 4];
            const float4 w2 = *(const float4*)&ws[(k + kk) * 64 + col0 + 8];
            const float4 w3 = *(const float4*)&ws[(k + kk) * 64 + col0 + 12];
            #pragma unroll
            for (int r = 0; r < 4; r++) {
                const float xr = (kk == 0) ? xv[r].x : (kk == 1) ? xv[r].y : (kk == 2) ? xv[r].z : xv[r].w;
                acc[r][0]  = fmaf(xr, w0.x, acc[r][0]);
                acc[r][1]  = fmaf(xr, w0.y, acc[r][1]);
                acc[r][2]  = fmaf(xr, w0.z, acc[r][2]);
                acc[r][3]  = fmaf(xr, w0.w, acc[r][3]);
                acc[r][4]  = fmaf(xr, w1.x, acc[r][4]);
                acc[r][5]  = fmaf(xr, w1.y, acc[r][5]);
                acc[r][6]  = fmaf(xr, w1.z, acc[r][6]);
                acc[r][7]  = fmaf(xr, w1.w, acc[r][7]);
                acc[r][8]  = fmaf(xr, w2.x, acc[r][8]);
                acc[r][9]  = fmaf(xr, w2.y, acc[r][9]);
                acc[r][10] = fmaf(xr, w2.z, acc[r][10]);
                acc[r][11] = fmaf(xr, w2.w, acc[r][11]);
                acc[r][12] = fmaf(xr, w3.x, acc[r][12]);
                acc[r][13] = fmaf(xr, w3.y, acc[r][13]);
                acc[r][14] = fmaf(xr, w3.z, acc[r][14]);
                acc[r][15] = fmaf(xr, w3.w, acc[r][15]);
            }
        }
    }

    if (!FINAL) {
        #pragma unroll
        for (int r = 0; r < 4; r++) {
            int row = row0 + rg + 32 * r;
            if (row < n) {
                float4* Yv = (float4*)(Y + (size_t)row * 64 + col0);
                Yv[0] = make_float4(acc[r][0], acc[r][1], acc[r][2], acc[r][3]);
                Yv[1] = make_float4(acc[r][4], acc[r][5], acc[r][6], acc[r][7]);
                Yv[2] = make_float4(acc[r][8], acc[r][9], acc[r][10], acc[r][11]);
                Yv[3] = make_float4(acc[r][12], acc[r][13], acc[r][14], acc[r][15]);
            }
        }
    } else {
        // + bias, then log_softmax over the 64 columns of each row (quad shuffles).
        float bv[16];
        #pragma unroll
        for (int c = 0; c < 16; c++) bv[c] = bias[col0 + c];
        #pragma unroll
        for (int r = 0; r < 4; r++) {
            #pragma unroll
            for (int c = 0; c < 16; c++) acc[r][c] += bv[c];
            float m = -1e30f;
            #pragma unroll
            for (int c = 0; c < 16; c++) m = fmaxf(m, acc[r][c]);
            m = fmaxf(m, __shfl_xor_sync(0xffffffffu, m, 1));
            m = fmaxf(m, __shfl_xor_sync(0xffffffffu, m, 2));
            float s = 0.f;
            #pragma unroll
            for (int c = 0; c < 16; c++) s += expf(acc[r][c] - m);
            s += __shfl_xor_sync(0xffffffffu, s, 1);
            s += __shfl_xor_sync(0xffffffffu, s, 2);
            const float lse = m + logf(s);
            int row = row0 + rg + 32 * r;
            if (row < n) {
                float4* Yv = (float4*)(Y + (size_t)row * 64 + col0);
                Yv[0] = make_float4(acc[r][0] - lse, acc[r][1] - lse, acc[r][2] - lse, acc[r][3] - lse);
                Yv[1] = make_float4(acc[r][4] - lse, acc[r][5] - lse, acc[r][6] - lse, acc[r][7] - lse);
                Yv[2] = make_float4(acc[r][8] - lse, acc[r][9] - lse, acc[r][10] - lse, acc[r][11] - lse);
                Yv[3] = make_float4(acc[r][12] - lse, acc[r][13] - lse, acc[r][14] - lse, acc[r][15] - lse);
            }
        }
    }
}

// ---------------- launcher ----------------

extern "C" void kernel_launch(void* const* d_in, const int* in_sizes, int n_in,
                              void* d_out, int out_size) {
    const float* x  = (const float*)d_in[0];
    const void*  ei = d_in[1];
    const float* W1 = (const float*)d_in[2];
    const float* b1 = (const float*)d_in[3];
    const float* W2 = (const float*)d_in[4];
    const float* b2 = (const float*)d_in[5];
    const float* W3 = (const float*)d_in[6];
    const float* b3 = (const float*)d_in[7];
    const float* W4 = (const float*)d_in[8];
    const float* b4 = (const float*)d_in[9];
    float* out = (float*)d_out;

    const int n = in_sizes[0] / 128;
    const int E = in_sizes[1] / 2;

    float *bufA, *bufB, *dinv, *Wc, *bc, *enrm;
    int *deg, *esrc, *edst;
    cudaGetSymbolAddress((void**)&bufA, g_bufA);
    cudaGetSymbolAddress((void**)&bufB, g_bufB);
    cudaGetSymbolAddress((void**)&deg,  g_deg);
    cudaGetSymbolAddress((void**)&dinv, g_dinv);
    cudaGetSymbolAddress((void**)&Wc,   g_Wc);
    cudaGetSymbolAddress((void**)&bc,   g_bc);
    cudaGetSymbolAddress((void**)&esrc, g_esrc);
    cudaGetSymbolAddress((void**)&edst, g_edst);
    cudaGetSymbolAddress((void**)&enrm, g_enrm);

    const int SM128 = (128 * (128 + 4) + 128 * 64) * 4;  // 100352 B
    const int SM64  = (128 * (64 + 4)  + 64 * 64)  * 4;  //  51200 B
    cudaFuncSetAttribute(gemm_kernel<128, false>, cudaFuncAttributeMaxDynamicSharedMemorySize, SM128);
    cudaFuncSetAttribute(gemm_kernel<64, false>,  cudaFuncAttributeMaxDynamicSharedMemorySize, SM64);
    cudaFuncSetAttribute(gemm_kernel<64, true>,   cudaFuncAttributeMaxDynamicSharedMemorySize, SM64);

    const int nThreads = 256;
    const int n16 = n * 16;         // float4 count for N*64 floats
    const int e4  = E * 4;          // scatter threads

    // detect edge dtype (writes g_is32)
    detect_kernel<<<1, 256>>>((const unsigned int*)ei, 2048);

    // degrees + pack edges (dtype-aware), dinv, per-edge norm
    zero4_kernel<<<(n / 4 + nThreads - 1) / nThreads, nThreads>>>((float4*)deg, n / 4);
    prep_edges_kernel<<<(E + nThreads - 1) / nThreads, nThreads>>>(ei, E, esrc, edst, deg);
    dinv_kernel<<<(n + nThreads - 1) / nThreads, nThreads>>>(deg, dinv, n);
    enrm_kernel<<<(E + nThreads - 1) / nThreads, nThreads>>>(esrc, edst, dinv, enrm, E);

    // collapse layers 3+4
    build_wc_kernel<<<(64 * 64 + 64 + nThreads - 1) / nThreads, nThreads>>>(W3, b3, W4, b4, Wc, bc);

    // ---- layer 1 ----
    gemm_kernel<128, false><<<(n + 127) / 128, 128, SM128>>>(x, W1, nullptr, bufA, n);
    zero4_kernel<<<(n16 + nThreads - 1) / nThreads, nThreads>>>((float4*)bufB, n16);
    scatter_kernel<<<(e4 + nThreads - 1) / nThreads, nThreads>>>(bufA, esrc, edst, enrm, bufB, E);
    finalize_kernel<<<(n16 + nThreads - 1) / nThreads, nThreads>>>(bufA, bufB, dinv, b1, n);

    // ---- layer 2 ----
    gemm_kernel<64, false><<<(n + 127) / 128, 128, SM64>>>(bufB, W2, nullptr, bufA, n);
    zero4_kernel<<<(n16 + nThreads - 1) / nThreads, nThreads>>>((float4*)bufB, n16);
    scatter_kernel<<<(e4 + nThreads - 1) / nThreads, nThreads>>>(bufA, esrc, edst, enrm, bufB, E);
    finalize_kernel<<<(n16 + nThreads - 1) / nThreads, nThreads>>>(bufA, bufB, dinv, b2, n);

    // ---- layers 3+4 (collapsed) + log_softmax ----
    gemm_kernel<64, true><<<(n + 127) / 128, 128, SM64>>>(bufB, Wc, bc, out, n);
}

// round 4
// speedup vs baseline: 1.4613x; 1.4613x over previous
#include <cuda_runtime.h>
#include <cuda_bf16.h>
#include <math.h>
#include <stdint.h>

#define MAXN 100000
#define MAXE 1600000
#define SCAN_B 512

// Scratch (device globals; no cudaMalloc allowed)
__device__ __align__(16) float g_bufA[MAXN * 64];
__device__ __align__(16) float g_bufB[MAXN * 64];
__device__ __align__(16) int   g_deg[MAXN];
__device__ __align__(16) float g_dinv[MAXN];
__device__ __align__(16) float g_Wc[64 * 64];
__device__ __align__(16) float g_bc[64];
__device__ __align__(16) int   g_esrc[MAXE];
__device__ __align__(16) int   g_edst[MAXE];
__device__ __align__(16) int   g_csrc[MAXE];   // CSR: src per slot (grouped by dst)
__device__ __align__(16) float g_cnrm[MAXE];   // CSR: norm per slot
__device__ __align__(16) int   g_off[MAXN + 1];
__device__ __align__(16) int   g_cursor[MAXN];
__device__ __align__(16) int   g_bsum[1024];
__device__ int g_is32;   // 1 if edge_index stored as int32, 0 if int64

// ---------------- dtype detection (device-side, deterministic) ----------------
__global__ void detect_kernel(const unsigned int* __restrict__ w, int nwords) {
    __shared__ int cnt;
    if (threadIdx.x == 0) cnt = 0;
    __syncthreads();
    int nz = 0;
    for (int i = threadIdx.x; i < 1024; i += blockDim.x) {
        int idx = 2 * i + 1;
        if (idx < nwords && w[idx] != 0u) nz++;
    }
    atomicAdd(&cnt, nz);
    __syncthreads();
    if (threadIdx.x == 0) g_is32 = (cnt > 10) ? 1 : 0;
}

// ---------------- prep ----------------

__global__ void zero4_kernel(float4* __restrict__ p, int n4) {
    int i = blockIdx.x * blockDim.x + threadIdx.x;
    if (i < n4) p[i] = make_float4(0.f, 0.f, 0.f, 0.f);
}

// Decode edges (either dtype), pack to int32, count degrees at dst.
__global__ void prep_edges_kernel(const void* __restrict__ ei, int E,
                                  int* __restrict__ esrc, int* __restrict__ edst,
                                  int* __restrict__ deg) {
    int e = blockIdx.x * blockDim.x + threadIdx.x;
    if (e >= E) return;
    int s, d;
    if (g_is32) {
        const int* p = (const int*)ei;
        s = p[e];
        d = p[E + e];
    } else {
        const long long* p = (const long long*)ei;
        s = (int)p[e];
        d = (int)p[E + e];
    }
    esrc[e] = s;
    edst[e] = d;
    atomicAdd(&deg[d], 1);
}

__global__ void dinv_kernel(const int* __restrict__ deg, float* __restrict__ dinv, int n) {
    int i = blockIdx.x * blockDim.x + threadIdx.x;
    if (i < n) dinv[i] = rsqrtf((float)deg[i] + 1.0f);
}

// ---- 3-kernel exclusive prefix scan of deg -> off, plus cursor init ----

__global__ void scan1_kernel(const int* __restrict__ deg, int* __restrict__ off,
                             int* __restrict__ bsum, int n) {
    __shared__ int sh[SCAN_B];
    int i = blockIdx.x * SCAN_B + threadIdx.x;
    int v = (i < n) ? deg[i] : 0;
    sh[threadIdx.x] = v;
    __syncthreads();
    #pragma unroll
    for (int d = 1; d < SCAN_B; d <<= 1) {
        int t = 0;
        if ((int)threadIdx.x >= d) t = sh[threadIdx.x - d];
        __syncthreads();
        if ((int)threadIdx.x >= d) sh[threadIdx.x] += t;
        __syncthreads();
    }
    if (i < n) off[i] = sh[threadIdx.x] - v;   // exclusive within block
    if (threadIdx.x == SCAN_B - 1) bsum[blockIdx.x] = sh[threadIdx.x];
}

__global__ void scan2_kernel(int* __restrict__ bsum, int nb) {
    __shared__ int sh[1024];
    int t = threadIdx.x;
    int v = (t < nb) ? bsum[t] : 0;
    sh[t] = v;
    __syncthreads();
    #pragma unroll
    for (int d = 1; d < 1024; d <<= 1) {
        int u = 0;
        if (t >= d) u = sh[t - d];
        __syncthreads();
        if (t >= d) sh[t] += u;
        __syncthreads();
    }
    if (t < nb) bsum[t] = sh[t] - v;   // exclusive block offsets
}

__global__ void scan3_kernel(int* __restrict__ off, const int* __restrict__ bsum,
                             int* __restrict__ cursor, int n, int E) {
    int i = blockIdx.x * SCAN_B + threadIdx.x;
    if (i < n) {
        int o = off[i] + bsum[blockIdx.x];
        off[i] = o;
        cursor[i] = o;
    }
    if (i == 0) off[n] = E;
}

// Group edges by dst (counting sort via cursor atomics); store src + precomputed norm.
__global__ void fill_kernel(const int* __restrict__ esrc, const int* __restrict__ edst,
                            const float* __restrict__ dinv, int* __restrict__ cursor,
                            int* __restrict__ csrc, float* __restrict__ cnrm, int E) {
    int e = blockIdx.x * blockDim.x + threadIdx.x;
    if (e >= E) return;
    int s = esrc[e];
    int d = edst[e];
    int slot = atomicAdd(&cursor[d], 1);
    csrc[slot] = s;
    cnrm[slot] = dinv[s] * dinv[d];
}

// Wc = W3 @ W4  (64x256 @ 256x64), bc = b3 @ W4 + b4
__global__ void build_wc_kernel(const float* __restrict__ W3, const float* __restrict__ b3,
                                const float* __restrict__ W4, const float* __restrict__ b4,
                                float* __restrict__ Wc, float* __restrict__ bc) {
    int o = blockIdx.x * blockDim.x + threadIdx.x;
    if (o < 64 * 64) {
        int i = o >> 6, j = o & 63;
        float s = 0.f;
        #pragma unroll 8
        for (int k = 0; k < 256; k++) s = fmaf(W3[i * 256 + k], W4[k * 64 + j], s);
        Wc[o] = s;
    } else if (o < 64 * 64 + 64) {
        int j = o - 64 * 64;
        float s = b4[j];
        #pragma unroll 8
        for (int k = 0; k < 256; k++) s = fmaf(b3[k], W4[k * 64 + j], s);
        bc[j] = s;
    }
}

// ---------------- gather aggregation (one warp per dst node) ----------------
// out[v] = relu( sum_{e in CSR[v]} h[src_e]*nrm_e + h[v]*dinv[v]^2 + b )
// Lane layout: q = lane&15 (channel quad), p = lane>>4 (2-way edge parallel).

__global__ void __launch_bounds__(256)
agg_kernel(const float* __restrict__ h, const int* __restrict__ off,
           const int* __restrict__ csrc, const float* __restrict__ cnrm,
           const float* __restrict__ dinv, const float* __restrict__ b,
           float* __restrict__ out, int n) {
    int gw = (blockIdx.x * 256 + threadIdx.x) >> 5;
    if (gw >= n) return;
    int lane = threadIdx.x & 31;
    int q = lane & 15;
    int p = lane >> 4;

    int beg = __ldg(&off[gw]);
    int end = __ldg(&off[gw + 1]);

    float4 acc = make_float4(0.f, 0.f, 0.f, 0.f);
    for (int i = beg + p; i < end; i += 2) {
        int s = __ldg(&csrc[i]);
        float w = __ldg(&cnrm[i]);
        float4 hv = __ldg(((const float4*)h) + (size_t)s * 16 + q);
        acc.x = fmaf(hv.x, w, acc.x);
        acc.y = fmaf(hv.y, w, acc.y);
        acc.z = fmaf(hv.z, w, acc.z);
        acc.w = fmaf(hv.w, w, acc.w);
    }
    // combine the two edge-parallel halves (lane ^ 16 has same q)
    acc.x += __shfl_xor_sync(0xffffffffu, acc.x, 16);
    acc.y += __shfl_xor_sync(0xffffffffu, acc.y, 16);
    acc.z += __shfl_xor_sync(0xffffffffu, acc.z, 16);
    acc.w += __shfl_xor_sync(0xffffffffu, acc.w, 16);

    if (p == 0) {
        float di = __ldg(&dinv[gw]);
        float sl = di * di;
        float4 hv = __ldg(((const float4*)h) + (size_t)gw * 16 + q);
        float4 bv = __ldg(((const float4*)b) + q);
        float4 o;
        o.x = fmaxf(fmaf(hv.x, sl, acc.x) + bv.x, 0.f);
        o.y = fmaxf(fmaf(hv.y, sl, acc.y) + bv.y, 0.f);
        o.z = fmaxf(fmaf(hv.z, sl, acc.z) + bv.z, 0.f);
        o.w = fmaxf(fmaf(hv.w, sl, acc.w) + bv.w, 0.f);
        ((float4*)out)[(size_t)gw * 16 + q] = o;
    }
}

// ---------------- skinny GEMM: Y[n,64] = X[n,K] @ W[K,64] (+bias, +log_softmax if FINAL) ----

template <int K, bool FINAL>
__global__ void __launch_bounds__(128, 2)
gemm_kernel(const float* __restrict__ X, const float* __restrict__ W,
            const float* __restrict__ bias, float* __restrict__ Y, int n) {
    extern __shared__ float smem[];
    const int PADK = K + 4;
    float* xs = smem;                  // 128 * PADK
    float* ws = smem + 128 * PADK;     // K * 64

    const int t = threadIdx.x;
    const int row0 = blockIdx.x * 128;

    {
        const float4* Wv = (const float4*)W;
        float4* wsv = (float4*)ws;
        #pragma unroll
        for (int i = t; i < K * 16; i += 128) wsv[i] = Wv[i];
    }
    {
        const int QK = K / 4;
        for (int i = t; i < 128 * QK; i += 128) {
            int r = i / QK, q = i % QK;
            int row = row0 + r;
            float4 v = make_float4(0.f, 0.f, 0.f, 0.f);
            if (row < n) v = ((const float4*)X)[(size_t)row * QK + q];
            *((float4*)&xs[r * PADK + q * 4]) = v;
        }
    }
    __syncthreads();

    const int cg = t & 3;
    const int rg = t >> 2;
    const int col0 = cg * 16;

    float acc[4][16];
    #pragma unroll
    for (int r = 0; r < 4; r++)
        #pragma unroll
        for (int c = 0; c < 16; c++) acc[r][c] = 0.f;

    #pragma unroll 2
    for (int k = 0; k < K; k += 4) {
        float4 xv[4];
        #pragma unroll
        for (int r = 0; r < 4; r++)
            xv[r] = *(const float4*)&xs[(rg + 32 * r) * PADK + k];
        #pragma unroll
        for (int kk = 0; kk < 4; kk++) {
            const float4 w0 = *(const float4*)&ws[(k + kk) * 64 + col0 + 0];
            const float4 w1 = *(const float4*)&ws[(k + kk) * 64 + col0 + 4];
            const float4 w2 = *(const float4*)&ws[(k + kk) * 64 + col0 + 8];
            const float4 w3 = *(const float4*)&ws[(k + kk) * 64 + col0 + 12];
            #pragma unroll
            for (int r = 0; r < 4; r++) {
                const float xr = (kk == 0) ? xv[r].x : (kk == 1) ? xv[r].y : (kk == 2) ? xv[r].z : xv[r].w;
                acc[r][0]  = fmaf(xr, w0.x, acc[r][0]);
                acc[r][1]  = fmaf(xr, w0.y, acc[r][1]);
                acc[r][2]  = fmaf(xr, w0.z, acc[r][2]);
                acc[r][3]  = fmaf(xr, w0.w, acc[r][3]);
                acc[r][4]  = fmaf(xr, w1.x, acc[r][4]);
                acc[r][5]  = fmaf(xr, w1.y, acc[r][5]);
                acc[r][6]  = fmaf(xr, w1.z, acc[r][6]);
                acc[r][7]  = fmaf(xr, w1.w, acc[r][7]);
                acc[r][8]  = fmaf(xr, w2.x, acc[r][8]);
                acc[r][9]  = fmaf(xr, w2.y, acc[r][9]);
                acc[r][10] = fmaf(xr, w2.z, acc[r][10]);
                acc[r][11] = fmaf(xr, w2.w, acc[r][11]);
                acc[r][12] = fmaf(xr, w3.x, acc[r][12]);
                acc[r][13] = fmaf(xr, w3.y, acc[r][13]);
                acc[r][14] = fmaf(xr, w3.z, acc[r][14]);
                acc[r][15] = fmaf(xr, w3.w, acc[r][15]);
            }
        }
    }

    if (!FINAL) {
        #pragma unroll
        for (int r = 0; r < 4; r++) {
            int row = row0 + rg + 32 * r;
            if (row < n) {
                float4* Yv = (float4*)(Y + (size_t)row * 64 + col0);
                Yv[0] = make_float4(acc[r][0], acc[r][1], acc[r][2], acc[r][3]);
                Yv[1] = make_float4(acc[r][4], acc[r][5], acc[r][6], acc[r][7]);
                Yv[2] = make_float4(acc[r][8], acc[r][9], acc[r][10], acc[r][11]);
                Yv[3] = make_float4(acc[r][12], acc[r][13], acc[r][14], acc[r][15]);
            }
        }
    } else {
        float bv[16];
        #pragma unroll
        for (int c = 0; c < 16; c++) bv[c] = bias[col0 + c];
        #pragma unroll
        for (int r = 0; r < 4; r++) {
            #pragma unroll
            for (int c = 0; c < 16; c++) acc[r][c] += bv[c];
            float m = -1e30f;
            #pragma unroll
            for (int c = 0; c < 16; c++) m = fmaxf(m, acc[r][c]);
            m = fmaxf(m, __shfl_xor_sync(0xffffffffu, m, 1));
            m = fmaxf(m, __shfl_xor_sync(0xffffffffu, m, 2));
            float s = 0.f;
            #pragma unroll
            for (int c = 0; c < 16; c++) s += expf(acc[r][c] - m);
            s += __shfl_xor_sync(0xffffffffu, s, 1);
            s += __shfl_xor_sync(0xffffffffu, s, 2);
            const float lse = m + logf(s);
            int row = row0 + rg + 32 * r;
            if (row < n) {
                float4* Yv = (float4*)(Y + (size_t)row * 64 + col0);
                Yv[0] = make_float4(acc[r][0] - lse, acc[r][1] - lse, acc[r][2] - lse, acc[r][3] - lse);
                Yv[1] = make_float4(acc[r][4] - lse, acc[r][5] - lse, acc[r][6] - lse, acc[r][7] - lse);
                Yv[2] = make_float4(acc[r][8] - lse, acc[r][9] - lse, acc[r][10] - lse, acc[r][11] - lse);
                Yv[3] = make_float4(acc[r][12] - lse, acc[r][13] - lse, acc[r][14] - lse, acc[r][15] - lse);
            }
        }
    }
}

// ---------------- launcher ----------------

extern "C" void kernel_launch(void* const* d_in, const int* in_sizes, int n_in,
                              void* d_out, int out_size) {
    const float* x  = (const float*)d_in[0];
    const void*  ei = d_in[1];
    const float* W1 = (const float*)d_in[2];
    const float* b1 = (const float*)d_in[3];
    const float* W2 = (const float*)d_in[4];
    const float* b2 = (const float*)d_in[5];
    const float* W3 = (const float*)d_in[6];
    const float* b3 = (const float*)d_in[7];
    const float* W4 = (const float*)d_in[8];
    const float* b4 = (const float*)d_in[9];
    float* out = (float*)d_out;

    const int n = in_sizes[0] / 128;
    const int E = in_sizes[1] / 2;

    float *bufA, *bufB, *dinv, *Wc, *bc, *cnrm;
    int *deg, *esrc, *edst, *csrc, *off, *cursor, *bsum;
    cudaGetSymbolAddress((void**)&bufA, g_bufA);
    cudaGetSymbolAddress((void**)&bufB, g_bufB);
    cudaGetSymbolAddress((void**)&deg,  g_deg);
    cudaGetSymbolAddress((void**)&dinv, g_dinv);
    cudaGetSymbolAddress((void**)&Wc,   g_Wc);
    cudaGetSymbolAddress((void**)&bc,   g_bc);
    cudaGetSymbolAddress((void**)&esrc, g_esrc);
    cudaGetSymbolAddress((void**)&edst, g_edst);
    cudaGetSymbolAddress((void**)&csrc, g_csrc);
    cudaGetSymbolAddress((void**)&cnrm, g_cnrm);
    cudaGetSymbolAddress((void**)&off,  g_off);
    cudaGetSymbolAddress((void**)&cursor, g_cursor);
    cudaGetSymbolAddress((void**)&bsum, g_bsum);

    const int SM128 = (128 * (128 + 4) + 128 * 64) * 4;  // 100352 B
    const int SM64  = (128 * (64 + 4)  + 64 * 64)  * 4;  //  51200 B
    cudaFuncSetAttribute(gemm_kernel<128, false>, cudaFuncAttributeMaxDynamicSharedMemorySize, SM128);
    cudaFuncSetAttribute(gemm_kernel<64, false>,  cudaFuncAttributeMaxDynamicSharedMemorySize, SM64);
    cudaFuncSetAttribute(gemm_kernel<64, true>,   cudaFuncAttributeMaxDynamicSharedMemorySize, SM64);

    const int nThreads = 256;
    const int nScanBlocks = (n + SCAN_B - 1) / SCAN_B;
    const int aggBlocks = (n * 32 + 255) / 256;

    // detect edge dtype (writes g_is32)
    detect_kernel<<<1, 256>>>((const unsigned int*)ei, 2048);

    // degrees + pack edges (dtype-aware), dinv
    zero4_kernel<<<(n / 4 + nThreads - 1) / nThreads, nThreads>>>((float4*)deg, n / 4);
    prep_edges_kernel<<<(E + nThreads - 1) / nThreads, nThreads>>>(ei, E, esrc, edst, deg);
    dinv_kernel<<<(n + nThreads - 1) / nThreads, nThreads>>>(deg, dinv, n);

    // CSR build: exclusive scan of deg -> off, cursor; counting sort by dst
    scan1_kernel<<<nScanBlocks, SCAN_B>>>(deg, off, bsum, n);
    scan2_kernel<<<1, 1024>>>(bsum, nScanBlocks);
    scan3_kernel<<<nScanBlocks, SCAN_B>>>(off, bsum, cursor, n, E);
    fill_kernel<<<(E + nThreads - 1) / nThreads, nThreads>>>(esrc, edst, dinv, cursor, csrc, cnrm, E);

    // collapse layers 3+4
    build_wc_kernel<<<(64 * 64 + 64 + nThreads - 1) / nThreads, nThreads>>>(W3, b3, W4, b4, Wc, bc);

    // ---- layer 1 ----
    gemm_kernel<128, false><<<(n + 127) / 128, 128, SM128>>>(x, W1, nullptr, bufA, n);
    agg_kernel<<<aggBlocks, 256>>>(bufA, off, csrc, cnrm, dinv, b1, bufB, n);

    // ---- layer 2 ----
    gemm_kernel<64, false><<<(n + 127) / 128, 128, SM64>>>(bufB, W2, nullptr, bufA, n);
    agg_kernel<<<aggBlocks, 256>>>(bufA, off, csrc, cnrm, dinv, b2, bufB, n);

    // ---- layers 3+4 (collapsed) + log_softmax ----
    gemm_kernel<64, true><<<(n + 127) / 128, 128, SM64>>>(bufB, Wc, bc, out, n);
}